// round 2
// baseline (speedup 1.0000x reference)
#include <cuda_runtime.h>
#include <math.h>

#define B_ 4
#define V_ 50000
#define C_ 256
#define K_ 128
#define LAMBDA 100.0f
#define NCHUNK 19
#define TPC 165            // 16-wide k-tiles per chunk (19*165=3135 >= 3125)
#define NTILES 3125        // V_/16 exactly

__device__ float g_part1[(size_t)NCHUNK * 8 * K_ * C_];  // [chunk][which*4+b][k][c]
__device__ float g_A[8 * K_ * C_];                       // [which][b][k][c]
__device__ float g_AA2[2 * 2 * B_ * K_ * K_];            // [chalf][t][b][k][l]

// ---------------------------------------------------------------------------
// GEMM1: A[which][b] (128x256) = E(128xV) * F(VxC), split-V into NCHUNK partials
// CTA: 128(M) x 128(N of 256) tile, ktile=16, 256 threads, 8x8 microtile.
// ---------------------------------------------------------------------------
__global__ __launch_bounds__(256, 2)
void gemm1(const float* __restrict__ fx, const float* __restrict__ fy,
           const float* __restrict__ ex, const float* __restrict__ ey)
{
    const int chunk = blockIdx.x, ntile = blockIdx.y, p = blockIdx.z;
    const int b = p >> 1, which = p & 1;
    const float* E = (which ? ey : ex) + (size_t)b * K_ * V_;
    const float* F = (which ? fy : fx) + (size_t)b * V_ * C_ + ntile * 128;
    float* out = g_part1 + ((size_t)chunk * 8 + which * 4 + b) * K_ * C_ + ntile * 128;

    __shared__ float Es[16][132];   // [v][k], padded rows (conflict-free scatter)
    __shared__ float Fs[16][128];   // [v][c]

    const int tid = threadIdx.x;
    const int lk = tid >> 1, lq = tid & 1;          // E loader: row lk, quad lq/lq+2
    const int fr = tid >> 5, fc = (tid & 31) << 2;  // F loader
    const int tm = tid >> 4, tn = tid & 15;         // compute grid 16x16

    const float* Erow = E + (size_t)lk * V_;

    float acc[8][8];
#pragma unroll
    for (int i = 0; i < 8; ++i)
#pragma unroll
        for (int j = 0; j < 8; ++j) acc[i][j] = 0.0f;

    const int t0 = chunk * TPC;
    const int t1 = (t0 + TPC < NTILES) ? (t0 + TPC) : NTILES;

    for (int t = t0; t < t1; ++t) {
        const int v = t << 4;
        float4 e0 = *(const float4*)(Erow + v + (lq << 2));
        float4 e1 = *(const float4*)(Erow + v + (lq << 2) + 8);
        float4 f0 = *(const float4*)(F + (size_t)(v + fr) * C_ + fc);
        float4 f1 = *(const float4*)(F + (size_t)(v + fr + 8) * C_ + fc);
        __syncthreads();
        const int r0 = lq << 2;
        Es[r0 + 0][lk] = e0.x; Es[r0 + 1][lk] = e0.y;
        Es[r0 + 2][lk] = e0.z; Es[r0 + 3][lk] = e0.w;
        Es[r0 + 8][lk] = e1.x; Es[r0 + 9][lk] = e1.y;
        Es[r0 + 10][lk] = e1.z; Es[r0 + 11][lk] = e1.w;
        *(float4*)&Fs[fr][fc] = f0;
        *(float4*)&Fs[fr + 8][fc] = f1;
        __syncthreads();
#pragma unroll
        for (int vv = 0; vv < 16; ++vv) {
            float4 a0 = *(const float4*)&Es[vv][tm << 2];
            float4 a1 = *(const float4*)&Es[vv][64 + (tm << 2)];
            float4 b0 = *(const float4*)&Fs[vv][tn << 2];
            float4 b1 = *(const float4*)&Fs[vv][64 + (tn << 2)];
            float a[8] = {a0.x, a0.y, a0.z, a0.w, a1.x, a1.y, a1.z, a1.w};
            float bb[8] = {b0.x, b0.y, b0.z, b0.w, b1.x, b1.y, b1.z, b1.w};
#pragma unroll
            for (int i = 0; i < 8; ++i)
#pragma unroll
                for (int j = 0; j < 8; ++j) acc[i][j] += a[i] * bb[j];
        }
    }

#pragma unroll
    for (int i = 0; i < 8; ++i) {
        const int row = (i < 4) ? ((tm << 2) + i) : (64 + (tm << 2) + i - 4);
        float4 o0 = {acc[i][0], acc[i][1], acc[i][2], acc[i][3]};
        float4 o1 = {acc[i][4], acc[i][5], acc[i][6], acc[i][7]};
        *(float4*)(out + (size_t)row * C_ + (tn << 2)) = o0;
        *(float4*)(out + (size_t)row * C_ + 64 + (tn << 2)) = o1;
    }
}

// ---------------------------------------------------------------------------
// Reduce split-V partials (fixed order -> deterministic)
// ---------------------------------------------------------------------------
__global__ void reduceA()
{
    const int i = blockIdx.x * 256 + threadIdx.x;   // 8*K_*C_ = 262144 total
    float s = 0.0f;
#pragma unroll
    for (int c = 0; c < NCHUNK; ++c) s += g_part1[(size_t)c * 8 * K_ * C_ + i];
    g_A[i] = s;
}

// ---------------------------------------------------------------------------
// GEMM2: AA_t[b](128x128) = A_t[b] * A_x[b]^T, split over 2 C-halves.
// ---------------------------------------------------------------------------
__global__ __launch_bounds__(256, 2)
void gemm2()
{
    const int cc = blockIdx.x;                      // c-half
    const int t = blockIdx.y & 1, b = blockIdx.y >> 1;
    const float* P = g_A + ((size_t)(t * B_ + b) * K_) * C_ + cc * 128;
    const float* Q = g_A + ((size_t)b * K_) * C_ + cc * 128;   // A_x
    float* out = g_AA2 + ((size_t)((cc * 2 + t) * B_ + b) * K_) * K_;

    __shared__ float Ps[16][132];
    __shared__ float Qs[16][132];

    const int tid = threadIdx.x;
    const int lk = tid >> 1, lq = tid & 1;
    const int tm = tid >> 4, tn = tid & 15;

    float acc[8][8];
#pragma unroll
    for (int i = 0; i < 8; ++i)
#pragma unroll
        for (int j = 0; j < 8; ++j) acc[i][j] = 0.0f;

    for (int kt = 0; kt < 8; ++kt) {
        const int c = kt << 4;
        float4 p0 = *(const float4*)(P + (size_t)lk * C_ + c + (lq << 2));
        float4 p1 = *(const float4*)(P + (size_t)lk * C_ + c + (lq << 2) + 8);
        float4 q0 = *(const float4*)(Q + (size_t)lk * C_ + c + (lq << 2));
        float4 q1 = *(const float4*)(Q + (size_t)lk * C_ + c + (lq << 2) + 8);
        __syncthreads();
        const int r0 = lq << 2;
        Ps[r0 + 0][lk] = p0.x; Ps[r0 + 1][lk] = p0.y; Ps[r0 + 2][lk] = p0.z; Ps[r0 + 3][lk] = p0.w;
        Ps[r0 + 8][lk] = p1.x; Ps[r0 + 9][lk] = p1.y; Ps[r0 + 10][lk] = p1.z; Ps[r0 + 11][lk] = p1.w;
        Qs[r0 + 0][lk] = q0.x; Qs[r0 + 1][lk] = q0.y; Qs[r0 + 2][lk] = q0.z; Qs[r0 + 3][lk] = q0.w;
        Qs[r0 + 8][lk] = q1.x; Qs[r0 + 9][lk] = q1.y; Qs[r0 + 10][lk] = q1.z; Qs[r0 + 11][lk] = q1.w;
        __syncthreads();
#pragma unroll
        for (int vv = 0; vv < 16; ++vv) {
            float4 a0 = *(const float4*)&Ps[vv][tm << 2];
            float4 a1 = *(const float4*)&Ps[vv][64 + (tm << 2)];
            float4 b0 = *(const float4*)&Qs[vv][tn << 2];
            float4 b1 = *(const float4*)&Qs[vv][64 + (tn << 2)];
            float a[8] = {a0.x, a0.y, a0.z, a0.w, a1.x, a1.y, a1.z, a1.w};
            float bb[8] = {b0.x, b0.y, b0.z, b0.w, b1.x, b1.y, b1.z, b1.w};
#pragma unroll
            for (int i = 0; i < 8; ++i)
#pragma unroll
                for (int j = 0; j < 8; ++j) acc[i][j] += a[i] * bb[j];
        }
    }

#pragma unroll
    for (int i = 0; i < 8; ++i) {
        const int row = (i < 4) ? ((tm << 2) + i) : (64 + (tm << 2) + i - 4);
        float4 o0 = {acc[i][0], acc[i][1], acc[i][2], acc[i][3]};
        float4 o1 = {acc[i][4], acc[i][5], acc[i][6], acc[i][7]};
        *(float4*)(out + (size_t)row * K_ + (tn << 2)) = o0;
        *(float4*)(out + (size_t)row * K_ + 64 + (tn << 2)) = o1;
    }
}

// ---------------------------------------------------------------------------
// Per-(b,i): mats = AA_xx[b] + LAMBDA*diag(mask(b,i,:)); Cholesky solve for
// rhs = AA_yx[b,i,:]. Packed lower triangle in smem. 128 threads, thread=row.
// ---------------------------------------------------------------------------
__global__ __launch_bounds__(128)
void solve(const float* __restrict__ evx, const float* __restrict__ evy,
           float* __restrict__ outp)
{
    __shared__ float Ml[K_ * (K_ + 1) / 2];   // 8256 floats
    __shared__ float invd[K_];
    __shared__ float r[K_];

    const int b = blockIdx.x >> 7, i = blockIdx.x & 127;
    const int t = threadIdx.x;

    // diagonal perturbation d_t = LAMBDA * mask[b][i][t]
    const float s = fmaxf(evx[b * K_ + K_ - 1], evy[b * K_ + K_ - 1]);
    const float g1 = sqrtf(evx[b * K_ + t] / s);
    const float g2 = sqrtf(evy[b * K_ + i] / s);
    const float d1 = g1 * g1 + 1.0f, d2 = g2 * g2 + 1.0f;
    const float re = g2 / d2 - g1 / d1;
    const float im = 1.0f / d2 - 1.0f / d1;
    const float dg = LAMBDA * (re * re + im * im);

    // load lower triangle of AA_xx[b] (sum of the 2 c-half partials), coalesced
    const float* X0 = g_AA2 + ((size_t)(0 * B_ + b) * K_) * K_;
    const float* X1 = g_AA2 + ((size_t)(2 * B_ + b) * K_) * K_;
    for (int m = 0; m < K_; ++m) {
        const float v = X0[m * K_ + t] + X1[m * K_ + t];
        if (t <= m) Ml[m * (m + 1) / 2 + t] = v + (t == m ? dg : 0.0f);
    }
    // rhs = AA_yx[b][i][:]
    const float* Y0 = g_AA2 + ((size_t)(1 * B_ + b) * K_ + i) * K_;
    const float* Y1 = g_AA2 + ((size_t)(3 * B_ + b) * K_ + i) * K_;
    r[t] = Y0[t] + Y1[t];
    __syncthreads();

    // Cholesky (right-looking, column-by-column)
    for (int j = 0; j < K_; ++j) {
        if (t == j) {
            const float v = Ml[j * (j + 1) / 2 + j];
            const float iv = rsqrtf(v);
            invd[j] = iv;
            Ml[j * (j + 1) / 2 + j] = v * iv;    // = sqrt(v)
        }
        __syncthreads();
        float lij = 0.0f;
        if (t > j) {
            lij = Ml[t * (t + 1) / 2 + j] * invd[j];
            Ml[t * (t + 1) / 2 + j] = lij;
        }
        __syncthreads();
        if (t > j) {
            const int base = t * (t + 1) / 2;
            for (int l = j + 1; l <= t; ++l)
                Ml[base + l] -= lij * Ml[l * (l + 1) / 2 + j];
        }
        __syncthreads();
    }
    // forward: L y = r
    for (int j = 0; j < K_; ++j) {
        if (t == j) r[j] *= invd[j];
        __syncthreads();
        if (t > j) r[t] -= Ml[t * (t + 1) / 2 + j] * r[j];
        __syncthreads();
    }
    // backward: L^T x = y
    for (int j = K_ - 1; j >= 0; --j) {
        if (t == j) r[j] *= invd[j];
        __syncthreads();
        if (t < j) r[t] -= Ml[j * (j + 1) / 2 + t] * r[j];
        __syncthreads();
    }
    outp[((size_t)(b * K_ + i)) * K_ + t] = r[t];
}

// ---------------------------------------------------------------------------
extern "C" void kernel_launch(void* const* d_in, const int* in_sizes, int n_in,
                              void* d_out, int out_size)
{
    const float* fx  = (const float*)d_in[0];
    const float* fy  = (const float*)d_in[1];
    const float* evx = (const float*)d_in[2];
    const float* evy = (const float*)d_in[3];
    const float* ex  = (const float*)d_in[4];
    const float* ey  = (const float*)d_in[5];
    float* out = (float*)d_out;

    gemm1<<<dim3(NCHUNK, 2, 8), 256>>>(fx, fy, ex, ey);
    reduceA<<<(8 * K_ * C_) / 256, 256>>>();
    gemm2<<<dim3(2, 8), 256>>>();
    solve<<<B_ * K_, 128>>>(evx, evy, out);
}

// round 3
// speedup vs baseline: 1.0004x; 1.0004x over previous
#include <cuda_runtime.h>
#include <math.h>

#define B_ 4
#define V_ 50000
#define C_ 256
#define K_ 128
#define LAMBDA 100.0f
#define NCHUNK 19
#define TPC 165            // 16-wide k-tiles per chunk (19*165=3135 >= 3125)
#define NTILES 3125        // V_/16 exactly

__device__ float g_part1[(size_t)NCHUNK * 8 * K_ * C_];  // [chunk][which*4+b][k][c]
__device__ float g_A[8 * K_ * C_];                       // [which][b][k][c]
__device__ float g_AA2[2 * 2 * B_ * K_ * K_];            // [chalf][t][b][k][l]

// ---------------------------------------------------------------------------
// GEMM1: A[which][b] (128x256) = E(128xV) * F(VxC), split-V into NCHUNK partials
// CTA: 128(M) x 128(N of 256) tile, ktile=16, 256 threads, 8x8 microtile.
// ---------------------------------------------------------------------------
__global__ __launch_bounds__(256, 2)
void gemm1(const float* __restrict__ fx, const float* __restrict__ fy,
           const float* __restrict__ ex, const float* __restrict__ ey)
{
    const int chunk = blockIdx.x, ntile = blockIdx.y, p = blockIdx.z;
    const int b = p >> 1, which = p & 1;
    const float* E = (which ? ey : ex) + (size_t)b * K_ * V_;
    const float* F = (which ? fy : fx) + (size_t)b * V_ * C_ + ntile * 128;
    float* out = g_part1 + ((size_t)chunk * 8 + which * 4 + b) * K_ * C_ + ntile * 128;

    __shared__ float Es[16][132];   // [v][k], padded rows (conflict-free scatter)
    __shared__ float Fs[16][128];   // [v][c]

    const int tid = threadIdx.x;
    const int lk = tid >> 1, lq = tid & 1;          // E loader: row lk, quad lq/lq+2
    const int fr = tid >> 5, fc = (tid & 31) << 2;  // F loader
    const int tm = tid >> 4, tn = tid & 15;         // compute grid 16x16

    const float* Erow = E + (size_t)lk * V_;

    float acc[8][8];
#pragma unroll
    for (int i = 0; i < 8; ++i)
#pragma unroll
        for (int j = 0; j < 8; ++j) acc[i][j] = 0.0f;

    const int t0 = chunk * TPC;
    const int t1 = (t0 + TPC < NTILES) ? (t0 + TPC) : NTILES;

    for (int t = t0; t < t1; ++t) {
        const int v = t << 4;
        float4 e0 = *(const float4*)(Erow + v + (lq << 2));
        float4 e1 = *(const float4*)(Erow + v + (lq << 2) + 8);
        float4 f0 = *(const float4*)(F + (size_t)(v + fr) * C_ + fc);
        float4 f1 = *(const float4*)(F + (size_t)(v + fr + 8) * C_ + fc);
        __syncthreads();
        const int r0 = lq << 2;
        Es[r0 + 0][lk] = e0.x; Es[r0 + 1][lk] = e0.y;
        Es[r0 + 2][lk] = e0.z; Es[r0 + 3][lk] = e0.w;
        Es[r0 + 8][lk] = e1.x; Es[r0 + 9][lk] = e1.y;
        Es[r0 + 10][lk] = e1.z; Es[r0 + 11][lk] = e1.w;
        *(float4*)&Fs[fr][fc] = f0;
        *(float4*)&Fs[fr + 8][fc] = f1;
        __syncthreads();
#pragma unroll
        for (int vv = 0; vv < 16; ++vv) {
            float4 a0 = *(const float4*)&Es[vv][tm << 2];
            float4 a1 = *(const float4*)&Es[vv][64 + (tm << 2)];
            float4 b0 = *(const float4*)&Fs[vv][tn << 2];
            float4 b1 = *(const float4*)&Fs[vv][64 + (tn << 2)];
            float a[8] = {a0.x, a0.y, a0.z, a0.w, a1.x, a1.y, a1.z, a1.w};
            float bb[8] = {b0.x, b0.y, b0.z, b0.w, b1.x, b1.y, b1.z, b1.w};
#pragma unroll
            for (int i = 0; i < 8; ++i)
#pragma unroll
                for (int j = 0; j < 8; ++j) acc[i][j] += a[i] * bb[j];
        }
    }

#pragma unroll
    for (int i = 0; i < 8; ++i) {
        const int row = (i < 4) ? ((tm << 2) + i) : (64 + (tm << 2) + i - 4);
        float4 o0 = {acc[i][0], acc[i][1], acc[i][2], acc[i][3]};
        float4 o1 = {acc[i][4], acc[i][5], acc[i][6], acc[i][7]};
        *(float4*)(out + (size_t)row * C_ + (tn << 2)) = o0;
        *(float4*)(out + (size_t)row * C_ + 64 + (tn << 2)) = o1;
    }
}

// ---------------------------------------------------------------------------
// Reduce split-V partials (fixed order -> deterministic)
// ---------------------------------------------------------------------------
__global__ void reduceA()
{
    const int i = blockIdx.x * 256 + threadIdx.x;   // 8*K_*C_ = 262144 total
    float s = 0.0f;
#pragma unroll
    for (int c = 0; c < NCHUNK; ++c) s += g_part1[(size_t)c * 8 * K_ * C_ + i];
    g_A[i] = s;
}

// ---------------------------------------------------------------------------
// GEMM2: AA_t[b](128x128) = A_t[b] * A_x[b]^T, split over 2 C-halves.
// ---------------------------------------------------------------------------
__global__ __launch_bounds__(256, 2)
void gemm2()
{
    const int cc = blockIdx.x;                      // c-half
    const int t = blockIdx.y & 1, b = blockIdx.y >> 1;
    const float* P = g_A + ((size_t)(t * B_ + b) * K_) * C_ + cc * 128;
    const float* Q = g_A + ((size_t)b * K_) * C_ + cc * 128;   // A_x
    float* out = g_AA2 + ((size_t)((cc * 2 + t) * B_ + b) * K_) * K_;

    __shared__ float Ps[16][132];
    __shared__ float Qs[16][132];

    const int tid = threadIdx.x;
    const int lk = tid >> 1, lq = tid & 1;
    const int tm = tid >> 4, tn = tid & 15;

    float acc[8][8];
#pragma unroll
    for (int i = 0; i < 8; ++i)
#pragma unroll
        for (int j = 0; j < 8; ++j) acc[i][j] = 0.0f;

    for (int kt = 0; kt < 8; ++kt) {
        const int c = kt << 4;
        float4 p0 = *(const float4*)(P + (size_t)lk * C_ + c + (lq << 2));
        float4 p1 = *(const float4*)(P + (size_t)lk * C_ + c + (lq << 2) + 8);
        float4 q0 = *(const float4*)(Q + (size_t)lk * C_ + c + (lq << 2));
        float4 q1 = *(const float4*)(Q + (size_t)lk * C_ + c + (lq << 2) + 8);
        __syncthreads();
        const int r0 = lq << 2;
        Ps[r0 + 0][lk] = p0.x; Ps[r0 + 1][lk] = p0.y; Ps[r0 + 2][lk] = p0.z; Ps[r0 + 3][lk] = p0.w;
        Ps[r0 + 8][lk] = p1.x; Ps[r0 + 9][lk] = p1.y; Ps[r0 + 10][lk] = p1.z; Ps[r0 + 11][lk] = p1.w;
        Qs[r0 + 0][lk] = q0.x; Qs[r0 + 1][lk] = q0.y; Qs[r0 + 2][lk] = q0.z; Qs[r0 + 3][lk] = q0.w;
        Qs[r0 + 8][lk] = q1.x; Qs[r0 + 9][lk] = q1.y; Qs[r0 + 10][lk] = q1.z; Qs[r0 + 11][lk] = q1.w;
        __syncthreads();
#pragma unroll
        for (int vv = 0; vv < 16; ++vv) {
            float4 a0 = *(const float4*)&Ps[vv][tm << 2];
            float4 a1 = *(const float4*)&Ps[vv][64 + (tm << 2)];
            float4 b0 = *(const float4*)&Qs[vv][tn << 2];
            float4 b1 = *(const float4*)&Qs[vv][64 + (tn << 2)];
            float a[8] = {a0.x, a0.y, a0.z, a0.w, a1.x, a1.y, a1.z, a1.w};
            float bb[8] = {b0.x, b0.y, b0.z, b0.w, b1.x, b1.y, b1.z, b1.w};
#pragma unroll
            for (int i = 0; i < 8; ++i)
#pragma unroll
                for (int j = 0; j < 8; ++j) acc[i][j] += a[i] * bb[j];
        }
    }

#pragma unroll
    for (int i = 0; i < 8; ++i) {
        const int row = (i < 4) ? ((tm << 2) + i) : (64 + (tm << 2) + i - 4);
        float4 o0 = {acc[i][0], acc[i][1], acc[i][2], acc[i][3]};
        float4 o1 = {acc[i][4], acc[i][5], acc[i][6], acc[i][7]};
        *(float4*)(out + (size_t)row * K_ + (tn << 2)) = o0;
        *(float4*)(out + (size_t)row * K_ + 64 + (tn << 2)) = o1;
    }
}

// ---------------------------------------------------------------------------
// Per-(b,i): mats = AA_xx[b] + LAMBDA*diag(mask(b,i,:)); Cholesky solve for
// rhs = AA_yx[b,i,:]. Packed lower triangle in smem. 128 threads, thread=row.
// ---------------------------------------------------------------------------
__global__ __launch_bounds__(128)
void solve(const float* __restrict__ evx, const float* __restrict__ evy,
           float* __restrict__ outp)
{
    __shared__ float Ml[K_ * (K_ + 1) / 2];   // 8256 floats
    __shared__ float invd[K_];
    __shared__ float r[K_];

    const int b = blockIdx.x >> 7, i = blockIdx.x & 127;
    const int t = threadIdx.x;

    // diagonal perturbation d_t = LAMBDA * mask[b][i][t]
    const float s = fmaxf(evx[b * K_ + K_ - 1], evy[b * K_ + K_ - 1]);
    const float g1 = sqrtf(evx[b * K_ + t] / s);
    const float g2 = sqrtf(evy[b * K_ + i] / s);
    const float d1 = g1 * g1 + 1.0f, d2 = g2 * g2 + 1.0f;
    const float re = g2 / d2 - g1 / d1;
    const float im = 1.0f / d2 - 1.0f / d1;
    const float dg = LAMBDA * (re * re + im * im);

    // load lower triangle of AA_xx[b] (sum of the 2 c-half partials), coalesced
    const float* X0 = g_AA2 + ((size_t)(0 * B_ + b) * K_) * K_;
    const float* X1 = g_AA2 + ((size_t)(2 * B_ + b) * K_) * K_;
    for (int m = 0; m < K_; ++m) {
        const float v = X0[m * K_ + t] + X1[m * K_ + t];
        if (t <= m) Ml[m * (m + 1) / 2 + t] = v + (t == m ? dg : 0.0f);
    }
    // rhs = AA_yx[b][i][:]
    const float* Y0 = g_AA2 + ((size_t)(1 * B_ + b) * K_ + i) * K_;
    const float* Y1 = g_AA2 + ((size_t)(3 * B_ + b) * K_ + i) * K_;
    r[t] = Y0[t] + Y1[t];
    __syncthreads();

    // Cholesky (right-looking, column-by-column)
    for (int j = 0; j < K_; ++j) {
        if (t == j) {
            const float v = Ml[j * (j + 1) / 2 + j];
            const float iv = rsqrtf(v);
            invd[j] = iv;
            Ml[j * (j + 1) / 2 + j] = v * iv;    // = sqrt(v)
        }
        __syncthreads();
        float lij = 0.0f;
        if (t > j) {
            lij = Ml[t * (t + 1) / 2 + j] * invd[j];
            Ml[t * (t + 1) / 2 + j] = lij;
        }
        __syncthreads();
        if (t > j) {
            const int base = t * (t + 1) / 2;
            for (int l = j + 1; l <= t; ++l)
                Ml[base + l] -= lij * Ml[l * (l + 1) / 2 + j];
        }
        __syncthreads();
    }
    // forward: L y = r
    for (int j = 0; j < K_; ++j) {
        if (t == j) r[j] *= invd[j];
        __syncthreads();
        if (t > j) r[t] -= Ml[t * (t + 1) / 2 + j] * r[j];
        __syncthreads();
    }
    // backward: L^T x = y
    for (int j = K_ - 1; j >= 0; --j) {
        if (t == j) r[j] *= invd[j];
        __syncthreads();
        if (t < j) r[t] -= Ml[j * (j + 1) / 2 + t] * r[j];
        __syncthreads();
    }
    outp[((size_t)(b * K_ + i)) * K_ + t] = r[t];
}

// ---------------------------------------------------------------------------
extern "C" void kernel_launch(void* const* d_in, const int* in_sizes, int n_in,
                              void* d_out, int out_size)
{
    const float* fx  = (const float*)d_in[0];
    const float* fy  = (const float*)d_in[1];
    const float* evx = (const float*)d_in[2];
    const float* evy = (const float*)d_in[3];
    const float* ex  = (const float*)d_in[4];
    const float* ey  = (const float*)d_in[5];
    float* out = (float*)d_out;

    gemm1<<<dim3(NCHUNK, 2, 8), 256>>>(fx, fy, ex, ey);
    reduceA<<<(8 * K_ * C_) / 256, 256>>>();
    gemm2<<<dim3(2, 8), 256>>>();
    solve<<<B_ * K_, 128>>>(evx, evy, out);
}